// round 17
// baseline (speedup 1.0000x reference)
#include <cuda_runtime.h>
#include <cstdint>

#define B_ 128
#define T_ 64
#define D_ 256
#define H_ 256
#define NT 512
#define NPAIR 64
#define HH (H_ * H_)

// R14 skeleton (carried-accumulator Wi overlap, producer/consumer layer
// pipeline) + (a) reduce spread over all 512 threads (1 elem each, symmetric
// barriers), (b) cp.async double-buffered staging of each pass's last 8
// k-rows per thread-slice (64KB/pass): issued one pass ahead during the
// reduce window, consumed via LDS. Pass parity is fixed per cell (4 passes):
// Wh0->buf1, Wh1->buf0, Wh2->buf1, WiN->buf0; bootstrap Wi(0)->buf0.

__device__ float g_h0buf[NPAIR][T_][2][H_];
__device__ int   g_flags[NPAIR * 32];

extern __shared__ float stg[];    // 2 x 16384 floats (2 x 64KB)

__device__ __forceinline__ uint32_t smem_u32(const void* p) {
    return (uint32_t)__cvta_generic_to_shared(p);
}
__device__ __forceinline__ void cpa16(uint32_t dst, const void* src) {
    asm volatile("cp.async.ca.shared.global [%0], [%1], 16;"
                 :: "r"(dst), "l"(src) : "memory");
}
__device__ __forceinline__ void cpa_commit() {
    asm volatile("cp.async.commit_group;" ::: "memory");
}
__device__ __forceinline__ void cpa_wait1() {
    asm volatile("cp.async.wait_group 1;" ::: "memory");
}
__device__ __forceinline__ void cpa_wait0() {
    asm volatile("cp.async.wait_group 0;" ::: "memory");
}
__device__ __forceinline__ float tanh_(float x) {
    return __fdividef(2.f, 1.f + __expf(-2.f * x)) - 1.f;
}
__device__ __forceinline__ float sigm_(float x) {
    return __fdividef(1.f, 1.f + __expf(-x));
}
__device__ __forceinline__ void f4fma(float4& a, float s, const float4 w) {
    a.x = fmaf(s, w.x, a.x); a.y = fmaf(s, w.y, a.y);
    a.z = fmaf(s, w.z, a.z); a.w = fmaf(s, w.w, a.w);
}
__device__ __forceinline__ void ld_grp(float4 (&w)[4], const float4* __restrict__ Wq, int g) {
    #pragma unroll
    for (int k = 0; k < 4; ++k) w[k] = Wq[g * 256 + k * 64];
}
__device__ __forceinline__ void ld_sgrp(float4 (&w)[4], const float4* __restrict__ sb, int g) {
    #pragma unroll
    for (int k = 0; k < 4; ++k) w[k] = sb[(g * 4 + k) * 64];
}
__device__ __forceinline__ void fma_grp(const float4 (&w)[4], const float4 A0,
                                        const float4 A1, float4& c0, float4& c1) {
    f4fma(c0, A0.x, w[0]); f4fma(c1, A1.x, w[0]);
    f4fma(c0, A0.y, w[1]); f4fma(c1, A1.y, w[1]);
    f4fma(c0, A0.z, w[2]); f4fma(c1, A1.z, w[2]);
    f4fma(c0, A0.w, w[3]); f4fma(c1, A1.w, w[3]);
}

// stage rows kc*32+24..+31 (8 rows x 256 cols per kc-chunk) of matrix M
// into one 16384-float buffer; 8 x 16B per thread; commits one group.
__device__ __forceinline__ void stage_cp(const float* __restrict__ M,
                                         float* __restrict__ buf, int tid) {
    const int kc = tid >> 6, l = tid & 63;
    const float* src = M + (size_t)(kc * 32 + 24) * 256 + l * 32;
    uint32_t dst = smem_u32(buf + kc * 2048 + l * 32);
    #pragma unroll
    for (int j = 0; j < 8; ++j)
        cpa16(dst + j * 16, src + j * 4);
    cpa_commit();
}

// One 256-k matrix pass. Entry: wp/w1/wa/wb = W k-groups 0-3 (rows 0-15 of
// slice). Rows 16-23 via inline LDG, rows 24-31 via LDS from sb.
// Exit: wp/w1 = Wn groups 0-1.
__device__ __forceinline__ void matpass(
    const float4* __restrict__ W, const float4* __restrict__ Wn,
    const float4* __restrict__ sb,
    const float4* __restrict__ a0, const float4* __restrict__ a1,
    float4 (&wp)[4], float4 (&w1)[4], float4 (&wa)[4], float4 (&wb)[4],
    float4& c0, float4& c1)
{
    fma_grp(wp, a0[0], a1[0], c0, c1); ld_grp(wp, Wn, 0);
    fma_grp(w1, a0[1], a1[1], c0, c1); ld_grp(w1, Wn, 1);
    fma_grp(wa, a0[2], a1[2], c0, c1); ld_grp(wa, W, 4);
    fma_grp(wb, a0[3], a1[3], c0, c1); ld_grp(wb, W, 5);
    fma_grp(wa, a0[4], a1[4], c0, c1); ld_sgrp(wa, sb, 0);
    fma_grp(wb, a0[5], a1[5], c0, c1); ld_sgrp(wb, sb, 1);
    fma_grp(wa, a0[6], a1[6], c0, c1);
    fma_grp(wb, a0[7], a1[7], c0, c1);
}

__global__ void reset_flags_kernel() {
    g_flags[threadIdx.x * 32] = 0;
}

__global__ void __launch_bounds__(NT, 1)
rnn_cpa_kernel(const float* __restrict__ x,       // [B,T,D]
               const float* __restrict__ hidden,  // [L,B,H]
               const float* __restrict__ Win0,    // [T,D,H]
               const float* __restrict__ Wh0,     // [T,3,H,H]
               const float* __restrict__ b0in,    // [T,3,H]
               const float* __restrict__ Win1,    // [T,H,H]
               const float* __restrict__ Wh1,     // [T,3,H,H]
               const float* __restrict__ b1in,    // [T,3,H]
               float* __restrict__ out,           // [B,T,H]
               float* __restrict__ hout)          // [L,B,H]
{
    __shared__ __align__(16) float xs[2][H_];
    __shared__ __align__(16) float hs[2][H_];
    __shared__ __align__(16) float n0s[2][H_];
    __shared__ __align__(16) float n1s[2][H_];
    __shared__ __align__(16) float bs[2][3][H_];
    __shared__ __align__(16) float4 part[8][2][64];

    const int tid = threadIdx.x;
    const int q = tid & 63;
    const int kc = tid >> 6;
    const int row = tid >> 8;       // reduce-element row
    const int col = tid & 255;      // reduce-element col
    const int pair = blockIdx.x >> 1;
    const int layer = blockIdx.x & 1;
    const int r0 = pair * 2;

    const float* Wi_base   = layer ? Win1 : Win0;
    const float* Wh_base   = layer ? Wh1 : Wh0;
    const float* bias_base = layer ? b1in : b0in;

    float* buf0 = stg;
    float* buf1 = stg + 16384;
    const float4* sb0 = reinterpret_cast<const float4*>(stg) + kc * 512 + q;
    const float4* sb1 = sb0 + 4096;

    const float* pf  = reinterpret_cast<const float*>(&part[0][0][0]);
    float* n0f = &n0s[0][0];
    float* n1f = &n1s[0][0];
    float* hsf = &hs[0][0];

    // ---- init ----
    hsf[tid] = hidden[((size_t)layer * B_ + r0 + row) * H_ + col];
    if (layer == 0)
        (&xs[0][0])[tid] = x[((size_t)(r0 + row) * T_) * D_ + col];
    if (tid < 192)
        reinterpret_cast<float4*>(&bs[0][0][0])[tid] =
            reinterpret_cast<const float4*>(bias_base)[tid];
    stage_cp(Wi_base, buf0, tid);                 // pass0: Wi(0) rows 24-31
    stage_cp(Wh_base, buf1, tid);                 // pass1: Wh0(0)
    if (layer == 1 && tid == 0) {
        int v;
        do {
            asm volatile("ld.acquire.gpu.global.s32 %0, [%1];"
                         : "=r"(v) : "l"(&g_flags[pair * 32]) : "memory");
            if (v < 1) __nanosleep(64);
        } while (v < 1);
    }
    cpa_wait1();                                  // pass0 staging complete
    __syncthreads();

    const int woff = kc * 32 * 64 + q;            // float4 units
    const float4* hs0 = reinterpret_cast<const float4*>(hs[0]) + kc * 8;
    const float4* hs1 = reinterpret_cast<const float4*>(hs[1]) + kc * 8;
    const float4* xs0 = reinterpret_cast<const float4*>(xs[0]) + kc * 8;
    const float4* xs1 = reinterpret_cast<const float4*>(xs[1]) + kc * 8;
    const float4* n00 = reinterpret_cast<const float4*>(n0s[0]) + kc * 8;
    const float4* n01 = reinterpret_cast<const float4*>(n0s[1]) + kc * 8;
    const float4* n10 = reinterpret_cast<const float4*>(n1s[0]) + kc * 8;
    const float4* n11 = reinterpret_cast<const float4*>(n1s[1]) + kc * 8;

    float4 wp[4], w1[4], wa[4], wb[4];
    float4 acc0, acc1;

    // ---- bootstrap pass: acc = in(0)@Wi(0) [buf0] ----
    {
        const float4* WqWi0 = reinterpret_cast<const float4*>(Wi_base) + woff;
        const float4* WqWh00 = reinterpret_cast<const float4*>(Wh_base) + woff;
        ld_grp(wp, WqWi0, 0); ld_grp(w1, WqWi0, 1);
        ld_grp(wa, WqWi0, 2); ld_grp(wb, WqWi0, 3);
        const float4* i0 = (layer == 0) ? xs0
            : reinterpret_cast<const float4*>(&g_h0buf[pair][0][0][0]) + kc * 8;
        const float4* i1 = (layer == 0) ? xs1
            : reinterpret_cast<const float4*>(&g_h0buf[pair][0][1][0]) + kc * 8;
        acc0 = make_float4(0.f,0.f,0.f,0.f); acc1 = acc0;
        matpass(WqWi0, WqWh00, sb0, i0, i1, wp, w1, wa, wb, acc0, acc1);
        ld_grp(wa, WqWh00, 2); ld_grp(wb, WqWh00, 3);
        __syncthreads();                          // S1
        stage_cp(Wh_base + HH, buf0, tid);        // pass2: Wh1(0) -> buf0
        cpa_wait1();                              // pass1 staging complete
        __syncthreads();                          // S2
    }

    for (int t = 0; t < T_; ++t) {
        const float* WhT = Wh_base + (size_t)t * 3 * HH;
        const float4* WqWh0 = reinterpret_cast<const float4*>(WhT) + woff;
        const float4* WqWh1 = WqWh0 + HH / 4;
        const float4* WqWh2 = WqWh0 + 2 * (HH / 4);
        const int tn = (t + 1 < T_) ? t + 1 : 0;
        const float* WiN_f = Wi_base + (size_t)tn * (D_ * H_);
        const float* Wh0N_f = Wh_base + (size_t)tn * 3 * HH;
        const float4* WqWiN = reinterpret_cast<const float4*>(WiN_f) + woff;
        const float4* WqWh0N = reinterpret_cast<const float4*>(Wh0N_f) + woff;
        const float* bsc = &bs[t & 1][0][0];
        const float4* bnext =
            reinterpret_cast<const float4*>(bias_base + (size_t)tn * 3 * H_);

        // ======== pass Wh0 [buf1]: acc += h@Wh0 ; reduce0 ========
        matpass(WqWh0, WqWh1, sb1, hs0, hs1, wp, w1, wa, wb, acc0, acc1);
        ld_grp(wa, WqWh1, 2); ld_grp(wb, WqWh1, 3);
        part[kc][0][q] = acc0; part[kc][1][q] = acc1;
        __syncthreads();
        {
            float s01 = pf[tid] + pf[512 + tid];
            float s23 = pf[1024 + tid] + pf[1536 + tid];
            float s45 = pf[2048 + tid] + pf[2560 + tid];
            float s67 = pf[3072 + tid] + pf[3584 + tid];
            float s = (s01 + s23) + (s45 + s67);
            n0f[tid] = tanh_(s + bsc[col]);
            if (tid < 192)                         // bias(t+1)
                reinterpret_cast<float4*>(&bs[(t + 1) & 1][0][0])[tid] = bnext[tid];
        }
        stage_cp(WhT + 2 * HH, buf1, tid);        // pass Wh2 -> buf1
        cpa_wait1();                              // Wh1 staging complete
        __syncthreads();

        // ======== pass Wh1 [buf0]: n0@Wh1 ; reduce1 ========
        acc0 = make_float4(0.f,0.f,0.f,0.f); acc1 = acc0;
        matpass(WqWh1, WqWh2, sb0, n00, n01, wp, w1, wa, wb, acc0, acc1);
        ld_grp(wa, WqWh2, 2); ld_grp(wb, WqWh2, 3);
        part[kc][0][q] = acc0; part[kc][1][q] = acc1;
        __syncthreads();
        {
            float s01 = pf[tid] + pf[512 + tid];
            float s23 = pf[1024 + tid] + pf[1536 + tid];
            float s45 = pf[2048 + tid] + pf[2560 + tid];
            float s67 = pf[3072 + tid] + pf[3584 + tid];
            float s = (s01 + s23) + (s45 + s67);
            n1f[tid] = fmaxf(s + bsc[H_ + col], 0.f) + n0f[tid];
            if (layer == 0 && t + 1 < T_ && tid >= 384) {   // x(t+1)
                int i = tid - 384;
                int rr = i >> 6, c4 = (i & 63) * 4;
                *reinterpret_cast<float4*>(&xs[rr][c4]) =
                    *reinterpret_cast<const float4*>(
                        &x[((size_t)(r0 + rr) * T_ + t + 1) * D_ + c4]);
            }
            if (layer == 1 && t + 1 < T_ && tid == 352) {   // h0(t+1) flag
                int v;
                do {
                    asm volatile("ld.acquire.gpu.global.s32 %0, [%1];"
                                 : "=r"(v) : "l"(&g_flags[pair * 32]) : "memory");
                    if (v < t + 2) __nanosleep(64);
                } while (v < t + 2);
            }
        }
        stage_cp(WiN_f, buf0, tid);               // pass WiN -> buf0
        cpa_wait1();                              // Wh2 staging complete
        __syncthreads();

        // ======== pass Wh2 [buf1]: n1@Wh2 ; reduce2 ========
        acc0 = make_float4(0.f,0.f,0.f,0.f); acc1 = acc0;
        matpass(WqWh2, WqWiN, sb1, n10, n11, wp, w1, wa, wb, acc0, acc1);
        ld_grp(wa, WqWiN, 2); ld_grp(wb, WqWiN, 3);
        part[kc][0][q] = acc0; part[kc][1][q] = acc1;
        __syncthreads();
        {
            float s01 = pf[tid] + pf[512 + tid];
            float s23 = pf[1024 + tid] + pf[1536 + tid];
            float s45 = pf[2048 + tid] + pf[2560 + tid];
            float s67 = pf[3072 + tid] + pf[3584 + tid];
            float s = (s01 + s23) + (s45 + s67);
            float gg = sigm_(s + bsc[2 * H_ + col]) + n0f[tid];
            float hn = 0.5f * (n1f[tid] + gg);
            hsf[tid] = hn;
            if (layer == 0) {
                __stcg(&g_h0buf[pair][t][row][col], hn);
                __threadfence();
            } else {
                out[((size_t)(r0 + row) * T_ + t) * H_ + col] = hn;
            }
        }
        stage_cp(Wh0N_f, buf1, tid);              // pass Wh0(t+1) -> buf1
        cpa_wait1();                              // WiN staging complete
        __syncthreads();
        if (layer == 0 && tid == 0)
            asm volatile("st.release.gpu.global.s32 [%0], %1;"
                         :: "l"(&g_flags[pair * 32]), "r"(t + 1) : "memory");

        // ======== pass WiN [buf0]: acc = in(t+1)@Wi(t+1) ========
        if (t + 1 < T_) {
            const float4* iN0 = (layer == 0) ? xs0
                : reinterpret_cast<const float4*>(&g_h0buf[pair][t + 1][0][0]) + kc * 8;
            const float4* iN1 = (layer == 0) ? xs1
                : reinterpret_cast<const float4*>(&g_h0buf[pair][t + 1][1][0]) + kc * 8;
            acc0 = make_float4(0.f,0.f,0.f,0.f); acc1 = acc0;
            matpass(WqWiN, WqWh0N, sb0, iN0, iN1, wp, w1, wa, wb, acc0, acc1);
            ld_grp(wa, WqWh0N, 2); ld_grp(wb, WqWh0N, 3);
            __syncthreads();                      // S1
            stage_cp(Wh0N_f + HH, buf0, tid);     // pass Wh1(t+1) -> buf0
            cpa_wait1();                          // Wh0(t+1) staging complete
            __syncthreads();                      // S2
        }
    }

    cpa_wait0();                                  // drain leftover groups
    hout[((size_t)layer * B_ + r0 + row) * H_ + col] = hsf[tid];
}

extern "C" void kernel_launch(void* const* d_in, const int* in_sizes, int n_in,
                              void* d_out, int out_size) {
    const float* x      = (const float*)d_in[0];
    const float* hidden = (const float*)d_in[1];
    const float* Win0   = (const float*)d_in[2];
    const float* Wh0    = (const float*)d_in[3];
    const float* b0     = (const float*)d_in[4];
    const float* Win1   = (const float*)d_in[5];
    const float* Wh1    = (const float*)d_in[6];
    const float* b1     = (const float*)d_in[7];

    float* out  = (float*)d_out;                  // [B,T,H]
    float* hout = out + (size_t)B_ * T_ * H_;     // [L,B,H]

    cudaFuncSetAttribute(rnn_cpa_kernel,
                         cudaFuncAttributeMaxDynamicSharedMemorySize, 131072);

    reset_flags_kernel<<<1, NPAIR>>>();
    rnn_cpa_kernel<<<2 * NPAIR, NT, 131072>>>(x, hidden, Win0, Wh0, b0,
                                              Win1, Wh1, b1, out, hout);
}